// round 3
// baseline (speedup 1.0000x reference)
#include <cuda_runtime.h>
#include <cstdint>
#include <cstddef>

// Problem constants
#define Bc   4
#define Sc   2048
#define Dc   1024
#define Hc   16
#define DKc  64
#define MR   (Bc * Sc)            // 8192 rows
#define OUT0 (MR * Dc)            // 8388608 elems for "out"
#define ATTN_ELEMS (268435456LL)  // 4*16*2048*2048

// Scratch (no dynamic allocation allowed)
__device__ float g_Q[MR * Dc];     // Q proj; reused as pre-LN x buffer
__device__ float g_Kb[MR * Dc];
__device__ float g_Vb[MR * Dc];
__device__ float g_CTX[MR * Dc];
__device__ float g_ATTN[268435456]; // fallback if attn is not part of d_out

// ---------------------------------------------------------------------------
// GEMM (NT): C[m,n] = sum_k A[m,k] * W[n,k] + bias[n] (+ residual[m,n])
// 128x128 tile, BK=8, 256 threads, 8x8 per thread.
// ---------------------------------------------------------------------------
__global__ __launch_bounds__(256) void gemm_nt_bias(
    const float* __restrict__ A, int lda,
    const float* __restrict__ W, int ldw,
    const float* __restrict__ bias,
    const float* __restrict__ residual,
    float* __restrict__ C, int ldc, int K)
{
    __shared__ float As[8][132];
    __shared__ float Bs[8][132];
    const int tid = threadIdx.x;
    const int m0 = blockIdx.y * 128;
    const int n0 = blockIdx.x * 128;
    const int lrow = tid >> 1;          // 0..127
    const int lcol = (tid & 1) * 4;     // 0 or 4
    const int ty = tid >> 4, tx = tid & 15;

    const float* Ap = A + (size_t)(m0 + lrow) * lda + lcol;
    const float* Bp = W + (size_t)(n0 + lrow) * ldw + lcol;

    float acc[8][8];
#pragma unroll
    for (int i = 0; i < 8; i++)
#pragma unroll
        for (int j = 0; j < 8; j++) acc[i][j] = 0.0f;

    for (int k0 = 0; k0 < K; k0 += 8) {
        float4 av = *(const float4*)(Ap + k0);
        float4 bv = *(const float4*)(Bp + k0);
        __syncthreads();
        As[lcol + 0][lrow] = av.x; As[lcol + 1][lrow] = av.y;
        As[lcol + 2][lrow] = av.z; As[lcol + 3][lrow] = av.w;
        Bs[lcol + 0][lrow] = bv.x; Bs[lcol + 1][lrow] = bv.y;
        Bs[lcol + 2][lrow] = bv.z; Bs[lcol + 3][lrow] = bv.w;
        __syncthreads();
#pragma unroll
        for (int kk = 0; kk < 8; kk++) {
            float a[8], b[8];
            *(float4*)(a)     = *(const float4*)&As[kk][ty * 4];
            *(float4*)(a + 4) = *(const float4*)&As[kk][64 + ty * 4];
            *(float4*)(b)     = *(const float4*)&Bs[kk][tx * 4];
            *(float4*)(b + 4) = *(const float4*)&Bs[kk][64 + tx * 4];
#pragma unroll
            for (int i = 0; i < 8; i++)
#pragma unroll
                for (int j = 0; j < 8; j++) acc[i][j] += a[i] * b[j];
        }
    }

    if (residual) {
#pragma unroll
        for (int i = 0; i < 8; i++) {
            int row = m0 + ((i < 4) ? (ty * 4 + i) : (64 + ty * 4 + i - 4));
#pragma unroll
            for (int j = 0; j < 8; j++) {
                int col = n0 + ((j < 4) ? (tx * 4 + j) : (64 + tx * 4 + j - 4));
                C[(size_t)row * ldc + col] =
                    acc[i][j] + bias[col] + residual[(size_t)row * ldc + col];
            }
        }
    } else {
#pragma unroll
        for (int i = 0; i < 8; i++) {
            int row = m0 + ((i < 4) ? (ty * 4 + i) : (64 + ty * 4 + i - 4));
#pragma unroll
            for (int j = 0; j < 8; j++) {
                int col = n0 + ((j < 4) ? (tx * 4 + j) : (64 + tx * 4 + j - 4));
                C[(size_t)row * ldc + col] = acc[i][j] + bias[col];
            }
        }
    }
}

// ---------------------------------------------------------------------------
// Scores GEMM (NT): per (b,h) scores[q,k] = dot(Qh[q,:], Kh[k,:]) / 8, +mask
// ---------------------------------------------------------------------------
__global__ __launch_bounds__(256) void gemm_scores(
    const float* __restrict__ Q, const float* __restrict__ Kt,
    const int* __restrict__ mask, float* __restrict__ Attn)
{
    const int bh = blockIdx.z;
    const int b = bh >> 4;
    const int h = bh & 15;
    const float* A  = Q  + (size_t)b * Sc * Dc + h * DKc;
    const float* Bw = Kt + (size_t)b * Sc * Dc + h * DKc;
    float* C = Attn + (size_t)bh * Sc * Sc;

    __shared__ float As[8][132];
    __shared__ float Bs[8][132];
    const int tid = threadIdx.x;
    const int m0 = blockIdx.y * 128;
    const int n0 = blockIdx.x * 128;
    const int lrow = tid >> 1;
    const int lcol = (tid & 1) * 4;
    const int ty = tid >> 4, tx = tid & 15;

    const float* Ap = A  + (size_t)(m0 + lrow) * Dc + lcol;
    const float* Bp = Bw + (size_t)(n0 + lrow) * Dc + lcol;

    float acc[8][8];
#pragma unroll
    for (int i = 0; i < 8; i++)
#pragma unroll
        for (int j = 0; j < 8; j++) acc[i][j] = 0.0f;

#pragma unroll
    for (int k0 = 0; k0 < DKc; k0 += 8) {
        float4 av = *(const float4*)(Ap + k0);
        float4 bv = *(const float4*)(Bp + k0);
        __syncthreads();
        As[lcol + 0][lrow] = av.x; As[lcol + 1][lrow] = av.y;
        As[lcol + 2][lrow] = av.z; As[lcol + 3][lrow] = av.w;
        Bs[lcol + 0][lrow] = bv.x; Bs[lcol + 1][lrow] = bv.y;
        Bs[lcol + 2][lrow] = bv.z; Bs[lcol + 3][lrow] = bv.w;
        __syncthreads();
#pragma unroll
        for (int kk = 0; kk < 8; kk++) {
            float a[8], b[8];
            *(float4*)(a)     = *(const float4*)&As[kk][ty * 4];
            *(float4*)(a + 4) = *(const float4*)&As[kk][64 + ty * 4];
            *(float4*)(b)     = *(const float4*)&Bs[kk][tx * 4];
            *(float4*)(b + 4) = *(const float4*)&Bs[kk][64 + tx * 4];
#pragma unroll
            for (int i = 0; i < 8; i++)
#pragma unroll
                for (int j = 0; j < 8; j++) acc[i][j] += a[i] * b[j];
        }
    }

#pragma unroll
    for (int i = 0; i < 8; i++) {
        int row = m0 + ((i < 4) ? (ty * 4 + i) : (64 + ty * 4 + i - 4));
#pragma unroll
        for (int j = 0; j < 8; j++) {
            int col = n0 + ((j < 4) ? (tx * 4 + j) : (64 + tx * 4 + j - 4));
            float v = acc[i][j] * 0.125f;
            if (mask[b * Sc + col] == 0) v = -1.0e9f;
            C[(size_t)row * Sc + col] = v;
        }
    }
}

// ---------------------------------------------------------------------------
// Row softmax over 2048 elements, in place.
// ---------------------------------------------------------------------------
__global__ __launch_bounds__(256) void softmax_rows(float* __restrict__ Attn)
{
    float* p = Attn + (size_t)blockIdx.x * Sc;
    const int t = threadIdx.x;
    __shared__ float red[256];

    float v[8];
    float mx = -1.0e30f;
#pragma unroll
    for (int i = 0; i < 8; i++) { v[i] = p[t + i * 256]; mx = fmaxf(mx, v[i]); }
    red[t] = mx; __syncthreads();
    for (int s = 128; s > 0; s >>= 1) { if (t < s) red[t] = fmaxf(red[t], red[t + s]); __syncthreads(); }
    mx = red[0];
    __syncthreads();

    float sum = 0.0f;
#pragma unroll
    for (int i = 0; i < 8; i++) { v[i] = __expf(v[i] - mx); sum += v[i]; }
    red[t] = sum; __syncthreads();
    for (int s = 128; s > 0; s >>= 1) { if (t < s) red[t] += red[t + s]; __syncthreads(); }
    float inv = 1.0f / red[0];

#pragma unroll
    for (int i = 0; i < 8; i++) p[t + i * 256] = v[i] * inv;
}

// ---------------------------------------------------------------------------
// Context GEMM (NN): per (b,h) ctx[q,d] = sum_k attn[q,k] * V[b,k,h*64+d]
// 128x64 tile, BK=16, 256 threads, 8x4 per thread.
// ---------------------------------------------------------------------------
__global__ __launch_bounds__(256) void gemm_ctx(
    const float* __restrict__ Attn, const float* __restrict__ V,
    float* __restrict__ CTX)
{
    const int bh = blockIdx.z;
    const int b = bh >> 4;
    const int h = bh & 15;
    const float* A  = Attn + (size_t)bh * Sc * Sc;
    const float* Bv = V + (size_t)b * Sc * Dc + h * DKc;
    float* C = CTX + (size_t)b * Sc * Dc + h * DKc;

    __shared__ float As[16][132];
    __shared__ float Bs[16][68];
    const int tid = threadIdx.x;
    const int m0 = blockIdx.y * 128;
    const int arow = tid >> 1;          // 0..127
    const int acol = (tid & 1) * 8;     // 0 or 8
    const int brow = tid >> 4;          // 0..15
    const int bcol = (tid & 15) * 4;    // 0..60
    const int ty = tid >> 4, tx = tid & 15;

    float acc[8][4];
#pragma unroll
    for (int i = 0; i < 8; i++)
#pragma unroll
        for (int j = 0; j < 4; j++) acc[i][j] = 0.0f;

    for (int k0 = 0; k0 < Sc; k0 += 16) {
        float4 a0 = *(const float4*)(A + (size_t)(m0 + arow) * Sc + k0 + acol);
        float4 a1 = *(const float4*)(A + (size_t)(m0 + arow) * Sc + k0 + acol + 4);
        float4 b4 = *(const float4*)(Bv + (size_t)(k0 + brow) * Dc + bcol);
        __syncthreads();
        As[acol + 0][arow] = a0.x; As[acol + 1][arow] = a0.y;
        As[acol + 2][arow] = a0.z; As[acol + 3][arow] = a0.w;
        As[acol + 4][arow] = a1.x; As[acol + 5][arow] = a1.y;
        As[acol + 6][arow] = a1.z; As[acol + 7][arow] = a1.w;
        *(float4*)&Bs[brow][bcol] = b4;
        __syncthreads();
#pragma unroll
        for (int kk = 0; kk < 16; kk++) {
            float a[8], bb[4];
            *(float4*)(a)     = *(const float4*)&As[kk][ty * 4];
            *(float4*)(a + 4) = *(const float4*)&As[kk][64 + ty * 4];
            *(float4*)(bb)    = *(const float4*)&Bs[kk][tx * 4];
#pragma unroll
            for (int i = 0; i < 8; i++)
#pragma unroll
                for (int j = 0; j < 4; j++) acc[i][j] += a[i] * bb[j];
        }
    }

#pragma unroll
    for (int i = 0; i < 8; i++) {
        int row = m0 + ((i < 4) ? (ty * 4 + i) : (64 + ty * 4 + i - 4));
#pragma unroll
        for (int j = 0; j < 4; j++) {
            int col = tx * 4 + j;
            C[(size_t)row * Dc + col] = acc[i][j];
        }
    }
}

// ---------------------------------------------------------------------------
// LayerNorm over last dim (1024), one block per row.
// ---------------------------------------------------------------------------
__global__ __launch_bounds__(256) void layernorm_rows(
    const float* __restrict__ X, const float* __restrict__ gamma,
    const float* __restrict__ beta, float* __restrict__ out)
{
    const int row = blockIdx.x;
    const float* x = X + (size_t)row * Dc;
    const int t = threadIdx.x;
    __shared__ float red[256];

    float v[4];
    float s = 0.0f;
#pragma unroll
    for (int i = 0; i < 4; i++) { v[i] = x[t + i * 256]; s += v[i]; }
    red[t] = s; __syncthreads();
    for (int w = 128; w > 0; w >>= 1) { if (t < w) red[t] += red[t + w]; __syncthreads(); }
    const float mu = red[0] * (1.0f / Dc);
    __syncthreads();

    float vs = 0.0f;
#pragma unroll
    for (int i = 0; i < 4; i++) { float d = v[i] - mu; vs += d * d; }
    red[t] = vs; __syncthreads();
    for (int w = 128; w > 0; w >>= 1) { if (t < w) red[t] += red[t + w]; __syncthreads(); }
    const float inv = rsqrtf(red[0] * (1.0f / Dc) + 1e-5f);

#pragma unroll
    for (int i = 0; i < 4; i++) {
        int c = t + i * 256;
        out[(size_t)row * Dc + c] = (v[i] - mu) * inv * gamma[c] + beta[c];
    }
}

// ---------------------------------------------------------------------------
extern "C" void kernel_launch(void* const* d_in, const int* in_sizes, int n_in,
                              void* d_out, int out_size)
{
    const float* query = (const float*)d_in[0];
    const float* key   = (const float*)d_in[1];
    const float* value = (const float*)d_in[2];
    const int*   mask  = (const int*)d_in[3];
    const float* Wq = (const float*)d_in[4];
    const float* bq = (const float*)d_in[5];
    const float* Wk = (const float*)d_in[6];
    const float* bk = (const float*)d_in[7];
    const float* Wv = (const float*)d_in[8];
    const float* bv = (const float*)d_in[9];
    const float* Wo = (const float*)d_in[10];
    const float* bo = (const float*)d_in[11];
    const float* gamma = (const float*)d_in[12];
    const float* beta  = (const float*)d_in[13];
    float* out = (float*)d_out;

    float *Qb, *Kb, *Vb, *Cb, *AttnScratch;
    cudaGetSymbolAddress((void**)&Qb, g_Q);
    cudaGetSymbolAddress((void**)&Kb, g_Kb);
    cudaGetSymbolAddress((void**)&Vb, g_Vb);
    cudaGetSymbolAddress((void**)&Cb, g_CTX);
    cudaGetSymbolAddress((void**)&AttnScratch, g_ATTN);

    // attn goes straight into d_out if the output buffer carries it (tuple concat)
    float* attn = ((long long)out_size >= (long long)OUT0 + ATTN_ELEMS)
                      ? (out + OUT0) : AttnScratch;

    dim3 gProj(Dc / 128, MR / 128);     // (8, 64)
    gemm_nt_bias<<<gProj, 256>>>(query, Dc, Wq, Dc, bq, nullptr, Qb, Dc, Dc);
    gemm_nt_bias<<<gProj, 256>>>(key,   Dc, Wk, Dc, bk, nullptr, Kb, Dc, Dc);
    gemm_nt_bias<<<gProj, 256>>>(value, Dc, Wv, Dc, bv, nullptr, Vb, Dc, Dc);

    dim3 gS(Sc / 128, Sc / 128, Bc * Hc);  // (16,16,64)
    gemm_scores<<<gS, 256>>>(Qb, Kb, mask, attn);

    softmax_rows<<<Bc * Hc * Sc, 256>>>(attn);  // 131072 rows

    dim3 gC(1, Sc / 128, Bc * Hc);      // (1,16,64)
    gemm_ctx<<<gC, 256>>>(attn, Vb, Cb);

    // out-proj + bias + residual -> x (reuse Qb as x buffer)
    gemm_nt_bias<<<gProj, 256>>>(Cb, Dc, Wo, Dc, bo, query, Qb, Dc, Dc);

    layernorm_rows<<<MR, 256>>>(Qb, gamma, beta, out);
}

// round 4
// speedup vs baseline: 1.1292x; 1.1292x over previous
#include <cuda_runtime.h>
#include <cstdint>
#include <cstddef>

// Problem constants
#define Bc   4
#define Sc   2048
#define Dc   1024
#define Hc   16
#define DKc  64
#define MR   (Bc * Sc)            // 8192 rows
#define OUT0 (MR * Dc)            // 8388608 elems for "out"
#define ATTN_ELEMS (268435456LL)  // 4*16*2048*2048

// Scratch (no dynamic allocation allowed)
__device__ float g_Q[MR * Dc];     // Q proj; reused as pre-LN x buffer
__device__ float g_Kb[MR * Dc];
__device__ float g_Vb[MR * Dc];
__device__ float g_CTX[MR * Dc];
__device__ float g_ATTN[268435456]; // fallback if attn is not part of d_out

// ---------------------------------------------------------------------------
// Fused QKV projection GEMM (NT), z selects {Q,K,V}.
// C[m,n] = sum_k A[m,k] * W[n,k] + bias[n]
// 128x128 tile, BK=8, 256 threads, 8x8/thread, register-prefetch pipeline.
// ---------------------------------------------------------------------------
__global__ __launch_bounds__(256) void qkv_proj(
    const float* __restrict__ q_in, const float* __restrict__ k_in,
    const float* __restrict__ v_in,
    const float* __restrict__ Wq, const float* __restrict__ Wk,
    const float* __restrict__ Wv,
    const float* __restrict__ bq, const float* __restrict__ bk,
    const float* __restrict__ bv,
    float* __restrict__ Qo, float* __restrict__ Ko, float* __restrict__ Vo)
{
    const int z = blockIdx.z;
    const float* A    = (z == 0) ? q_in : (z == 1) ? k_in : v_in;
    const float* W    = (z == 0) ? Wq   : (z == 1) ? Wk   : Wv;
    const float* bias = (z == 0) ? bq   : (z == 1) ? bk   : bv;
    float*       C    = (z == 0) ? Qo   : (z == 1) ? Ko   : Vo;

    __shared__ float As[8][132];
    __shared__ float Bs[8][132];
    const int tid = threadIdx.x;
    const int m0 = blockIdx.y * 128;
    const int n0 = blockIdx.x * 128;
    const int lrow = tid >> 1;          // 0..127
    const int lcol = (tid & 1) * 4;     // 0 or 4
    const int ty = tid >> 4, tx = tid & 15;

    const float* Ap = A + (size_t)(m0 + lrow) * Dc + lcol;
    const float* Bp = W + (size_t)(n0 + lrow) * Dc + lcol;

    float acc[8][8];
#pragma unroll
    for (int i = 0; i < 8; i++)
#pragma unroll
        for (int j = 0; j < 8; j++) acc[i][j] = 0.0f;

    float4 av = *(const float4*)(Ap);
    float4 bv4 = *(const float4*)(Bp);

    for (int k0 = 0; k0 < Dc; k0 += 8) {
        __syncthreads();
        As[lcol + 0][lrow] = av.x; As[lcol + 1][lrow] = av.y;
        As[lcol + 2][lrow] = av.z; As[lcol + 3][lrow] = av.w;
        Bs[lcol + 0][lrow] = bv4.x; Bs[lcol + 1][lrow] = bv4.y;
        Bs[lcol + 2][lrow] = bv4.z; Bs[lcol + 3][lrow] = bv4.w;
        __syncthreads();
        float4 av2, bv2;
        if (k0 + 8 < Dc) {
            av2 = *(const float4*)(Ap + k0 + 8);
            bv2 = *(const float4*)(Bp + k0 + 8);
        }
#pragma unroll
        for (int kk = 0; kk < 8; kk++) {
            float a[8], b[8];
            *(float4*)(a)     = *(const float4*)&As[kk][ty * 4];
            *(float4*)(a + 4) = *(const float4*)&As[kk][64 + ty * 4];
            *(float4*)(b)     = *(const float4*)&Bs[kk][tx * 4];
            *(float4*)(b + 4) = *(const float4*)&Bs[kk][64 + tx * 4];
#pragma unroll
            for (int i = 0; i < 8; i++)
#pragma unroll
                for (int j = 0; j < 8; j++) acc[i][j] += a[i] * b[j];
        }
        av = av2; bv4 = bv2;
    }

#pragma unroll
    for (int i = 0; i < 8; i++) {
        int row = m0 + ((i < 4) ? (ty * 4 + i) : (64 + ty * 4 + i - 4));
#pragma unroll
        for (int j = 0; j < 8; j++) {
            int col = n0 + ((j < 4) ? (tx * 4 + j) : (64 + tx * 4 + j - 4));
            C[(size_t)row * Dc + col] = acc[i][j] + bias[col];
        }
    }
}

// ---------------------------------------------------------------------------
// Output projection (NT) + bias + residual. Same pipeline structure.
// ---------------------------------------------------------------------------
__global__ __launch_bounds__(256) void gemm_out_proj(
    const float* __restrict__ A, const float* __restrict__ W,
    const float* __restrict__ bias, const float* __restrict__ residual,
    float* __restrict__ C)
{
    __shared__ float As[8][132];
    __shared__ float Bs[8][132];
    const int tid = threadIdx.x;
    const int m0 = blockIdx.y * 128;
    const int n0 = blockIdx.x * 128;
    const int lrow = tid >> 1;
    const int lcol = (tid & 1) * 4;
    const int ty = tid >> 4, tx = tid & 15;

    const float* Ap = A + (size_t)(m0 + lrow) * Dc + lcol;
    const float* Bp = W + (size_t)(n0 + lrow) * Dc + lcol;

    float acc[8][8];
#pragma unroll
    for (int i = 0; i < 8; i++)
#pragma unroll
        for (int j = 0; j < 8; j++) acc[i][j] = 0.0f;

    float4 av = *(const float4*)(Ap);
    float4 bv4 = *(const float4*)(Bp);

    for (int k0 = 0; k0 < Dc; k0 += 8) {
        __syncthreads();
        As[lcol + 0][lrow] = av.x; As[lcol + 1][lrow] = av.y;
        As[lcol + 2][lrow] = av.z; As[lcol + 3][lrow] = av.w;
        Bs[lcol + 0][lrow] = bv4.x; Bs[lcol + 1][lrow] = bv4.y;
        Bs[lcol + 2][lrow] = bv4.z; Bs[lcol + 3][lrow] = bv4.w;
        __syncthreads();
        float4 av2, bv2;
        if (k0 + 8 < Dc) {
            av2 = *(const float4*)(Ap + k0 + 8);
            bv2 = *(const float4*)(Bp + k0 + 8);
        }
#pragma unroll
        for (int kk = 0; kk < 8; kk++) {
            float a[8], b[8];
            *(float4*)(a)     = *(const float4*)&As[kk][ty * 4];
            *(float4*)(a + 4) = *(const float4*)&As[kk][64 + ty * 4];
            *(float4*)(b)     = *(const float4*)&Bs[kk][tx * 4];
            *(float4*)(b + 4) = *(const float4*)&Bs[kk][64 + tx * 4];
#pragma unroll
            for (int i = 0; i < 8; i++)
#pragma unroll
                for (int j = 0; j < 8; j++) acc[i][j] += a[i] * b[j];
        }
        av = av2; bv4 = bv2;
    }

#pragma unroll
    for (int i = 0; i < 8; i++) {
        int row = m0 + ((i < 4) ? (ty * 4 + i) : (64 + ty * 4 + i - 4));
#pragma unroll
        for (int j = 0; j < 8; j++) {
            int col = n0 + ((j < 4) ? (tx * 4 + j) : (64 + tx * 4 + j - 4));
            C[(size_t)row * Dc + col] =
                acc[i][j] + bias[col] + residual[(size_t)row * Dc + col];
        }
    }
}

// ---------------------------------------------------------------------------
// Scores GEMM (NT): per (b,h) scores[q,k] = dot(Qh[q,:], Kh[k,:]) / 8, +mask
// BK=32 (2 chunks over K=64), register prefetch, 4 syncs total.
// ---------------------------------------------------------------------------
__global__ __launch_bounds__(256, 2) void gemm_scores(
    const float* __restrict__ Q, const float* __restrict__ Kt,
    const int* __restrict__ mask, float* __restrict__ Attn)
{
    const int bh = blockIdx.z;
    const int b = bh >> 4;
    const int h = bh & 15;
    const float* A  = Q  + (size_t)b * Sc * Dc + h * DKc;
    const float* Bw = Kt + (size_t)b * Sc * Dc + h * DKc;
    float* C = Attn + (size_t)bh * Sc * Sc;

    __shared__ float As[32][132];
    __shared__ float Bs[32][132];
    const int tid = threadIdx.x;
    const int m0 = blockIdx.y * 128;
    const int n0 = blockIdx.x * 128;
    const int lrow = tid >> 1;          // 0..127
    const int lk = (tid & 1) * 16;      // 0 or 16 (within 32-k chunk)
    const int ty = tid >> 4, tx = tid & 15;

    const float* Ap = A  + (size_t)(m0 + lrow) * Dc + lk;
    const float* Bp = Bw + (size_t)(n0 + lrow) * Dc + lk;

    float acc[8][8];
#pragma unroll
    for (int i = 0; i < 8; i++)
#pragma unroll
        for (int j = 0; j < 8; j++) acc[i][j] = 0.0f;

    float4 qa[4], kb[4];
#pragma unroll
    for (int i = 0; i < 4; i++) {
        qa[i] = *(const float4*)(Ap + 4 * i);
        kb[i] = *(const float4*)(Bp + 4 * i);
    }

#pragma unroll
    for (int k0 = 0; k0 < DKc; k0 += 32) {
        __syncthreads();
#pragma unroll
        for (int i = 0; i < 4; i++) {
            As[lk + 4 * i + 0][lrow] = qa[i].x;
            As[lk + 4 * i + 1][lrow] = qa[i].y;
            As[lk + 4 * i + 2][lrow] = qa[i].z;
            As[lk + 4 * i + 3][lrow] = qa[i].w;
            Bs[lk + 4 * i + 0][lrow] = kb[i].x;
            Bs[lk + 4 * i + 1][lrow] = kb[i].y;
            Bs[lk + 4 * i + 2][lrow] = kb[i].z;
            Bs[lk + 4 * i + 3][lrow] = kb[i].w;
        }
        __syncthreads();
        if (k0 + 32 < DKc) {
#pragma unroll
            for (int i = 0; i < 4; i++) {
                qa[i] = *(const float4*)(Ap + k0 + 32 + 4 * i);
                kb[i] = *(const float4*)(Bp + k0 + 32 + 4 * i);
            }
        }
#pragma unroll
        for (int kk = 0; kk < 32; kk++) {
            float a[8], bb[8];
            *(float4*)(a)      = *(const float4*)&As[kk][ty * 4];
            *(float4*)(a + 4)  = *(const float4*)&As[kk][64 + ty * 4];
            *(float4*)(bb)     = *(const float4*)&Bs[kk][tx * 4];
            *(float4*)(bb + 4) = *(const float4*)&Bs[kk][64 + tx * 4];
#pragma unroll
            for (int i = 0; i < 8; i++)
#pragma unroll
                for (int j = 0; j < 8; j++) acc[i][j] += a[i] * bb[j];
        }
    }

#pragma unroll
    for (int i = 0; i < 8; i++) {
        int row = m0 + ((i < 4) ? (ty * 4 + i) : (64 + ty * 4 + i - 4));
#pragma unroll
        for (int j = 0; j < 8; j++) {
            int col = n0 + ((j < 4) ? (tx * 4 + j) : (64 + tx * 4 + j - 4));
            float v = acc[i][j] * 0.125f;
            if (mask[b * Sc + col] == 0) v = -1.0e9f;
            C[(size_t)row * Sc + col] = v;
        }
    }
}

// ---------------------------------------------------------------------------
// Row softmax over 2048 elements, in place. Shuffle reductions.
// ---------------------------------------------------------------------------
__global__ __launch_bounds__(256) void softmax_rows(float* __restrict__ Attn)
{
    float* p = Attn + (size_t)blockIdx.x * Sc;
    const int t = threadIdx.x;
    const int lane = t & 31, w = t >> 5;
    __shared__ float red[8];

    float v[8];
    float mx = -1.0e30f;
#pragma unroll
    for (int i = 0; i < 8; i++) { v[i] = p[t + i * 256]; mx = fmaxf(mx, v[i]); }
#pragma unroll
    for (int off = 16; off > 0; off >>= 1)
        mx = fmaxf(mx, __shfl_xor_sync(0xffffffffu, mx, off));
    if (lane == 0) red[w] = mx;
    __syncthreads();
    float m = red[0];
#pragma unroll
    for (int i = 1; i < 8; i++) m = fmaxf(m, red[i]);
    __syncthreads();   // everyone read red before reuse

    float sum = 0.0f;
#pragma unroll
    for (int i = 0; i < 8; i++) { v[i] = __expf(v[i] - m); sum += v[i]; }
#pragma unroll
    for (int off = 16; off > 0; off >>= 1)
        sum += __shfl_xor_sync(0xffffffffu, sum, off);
    if (lane == 0) red[w] = sum;
    __syncthreads();
    float s = 0.0f;
#pragma unroll
    for (int i = 0; i < 8; i++) s += red[i];
    float inv = 1.0f / s;

#pragma unroll
    for (int i = 0; i < 8; i++) p[t + i * 256] = v[i] * inv;
}

// ---------------------------------------------------------------------------
// Context GEMM (NN): per (b,h) ctx[q,d] = sum_k attn[q,k] * V[b,k,h*64+d]
// 128x64 tile, BK=16, 256 threads, 8x4/thread, register-prefetch pipeline.
// ---------------------------------------------------------------------------
__global__ __launch_bounds__(256) void gemm_ctx(
    const float* __restrict__ Attn, const float* __restrict__ V,
    float* __restrict__ CTX)
{
    const int bh = blockIdx.z;
    const int b = bh >> 4;
    const int h = bh & 15;
    const float* A  = Attn + (size_t)bh * Sc * Sc;
    const float* Bv = V + (size_t)b * Sc * Dc + h * DKc;
    float* C = CTX + (size_t)b * Sc * Dc + h * DKc;

    __shared__ float As[16][132];
    __shared__ float Bs[16][68];
    const int tid = threadIdx.x;
    const int m0 = blockIdx.y * 128;
    const int arow = tid >> 1;          // 0..127
    const int acol = (tid & 1) * 8;     // 0 or 8
    const int brow = tid >> 4;          // 0..15
    const int bcol = (tid & 15) * 4;    // 0..60
    const int ty = tid >> 4, tx = tid & 15;

    float acc[8][4];
#pragma unroll
    for (int i = 0; i < 8; i++)
#pragma unroll
        for (int j = 0; j < 4; j++) acc[i][j] = 0.0f;

    const float* Arow = A + (size_t)(m0 + arow) * Sc + acol;

    float4 a0 = *(const float4*)(Arow);
    float4 a1 = *(const float4*)(Arow + 4);
    float4 b4 = *(const float4*)(Bv + (size_t)brow * Dc + bcol);

    for (int k0 = 0; k0 < Sc; k0 += 16) {
        __syncthreads();
        As[acol + 0][arow] = a0.x; As[acol + 1][arow] = a0.y;
        As[acol + 2][arow] = a0.z; As[acol + 3][arow] = a0.w;
        As[acol + 4][arow] = a1.x; As[acol + 5][arow] = a1.y;
        As[acol + 6][arow] = a1.z; As[acol + 7][arow] = a1.w;
        *(float4*)&Bs[brow][bcol] = b4;
        __syncthreads();
        float4 a0n, a1n, b4n;
        if (k0 + 16 < Sc) {
            a0n = *(const float4*)(Arow + k0 + 16);
            a1n = *(const float4*)(Arow + k0 + 20);
            b4n = *(const float4*)(Bv + (size_t)(k0 + 16 + brow) * Dc + bcol);
        }
#pragma unroll
        for (int kk = 0; kk < 16; kk++) {
            float a[8], bb[4];
            *(float4*)(a)     = *(const float4*)&As[kk][ty * 4];
            *(float4*)(a + 4) = *(const float4*)&As[kk][64 + ty * 4];
            *(float4*)(bb)    = *(const float4*)&Bs[kk][tx * 4];
#pragma unroll
            for (int i = 0; i < 8; i++)
#pragma unroll
                for (int j = 0; j < 4; j++) acc[i][j] += a[i] * bb[j];
        }
        a0 = a0n; a1 = a1n; b4 = b4n;
    }

#pragma unroll
    for (int i = 0; i < 8; i++) {
        int row = m0 + ((i < 4) ? (ty * 4 + i) : (64 + ty * 4 + i - 4));
#pragma unroll
        for (int j = 0; j < 4; j++) {
            int col = tx * 4 + j;
            C[(size_t)row * Dc + col] = acc[i][j];
        }
    }
}

// ---------------------------------------------------------------------------
// LayerNorm over last dim (1024), one block per row.
// ---------------------------------------------------------------------------
__global__ __launch_bounds__(256) void layernorm_rows(
    const float* __restrict__ X, const float* __restrict__ gamma,
    const float* __restrict__ beta, float* __restrict__ out)
{
    const int row = blockIdx.x;
    const float* x = X + (size_t)row * Dc;
    const int t = threadIdx.x;
    const int lane = t & 31, w = t >> 5;
    __shared__ float red[8];

    float v[4];
    float s = 0.0f;
#pragma unroll
    for (int i = 0; i < 4; i++) { v[i] = x[t + i * 256]; s += v[i]; }
#pragma unroll
    for (int off = 16; off > 0; off >>= 1)
        s += __shfl_xor_sync(0xffffffffu, s, off);
    if (lane == 0) red[w] = s;
    __syncthreads();
    float tot = 0.0f;
#pragma unroll
    for (int i = 0; i < 8; i++) tot += red[i];
    const float mu = tot * (1.0f / Dc);
    __syncthreads();

    float vs = 0.0f;
#pragma unroll
    for (int i = 0; i < 4; i++) { float d = v[i] - mu; vs += d * d; }
#pragma unroll
    for (int off = 16; off > 0; off >>= 1)
        vs += __shfl_xor_sync(0xffffffffu, vs, off);
    if (lane == 0) red[w] = vs;
    __syncthreads();
    float vtot = 0.0f;
#pragma unroll
    for (int i = 0; i < 8; i++) vtot += red[i];
    const float inv = rsqrtf(vtot * (1.0f / Dc) + 1e-5f);

#pragma unroll
    for (int i = 0; i < 4; i++) {
        int c = t + i * 256;
        out[(size_t)row * Dc + c] = (v[i] - mu) * inv * gamma[c] + beta[c];
    }
}

// ---------------------------------------------------------------------------
extern "C" void kernel_launch(void* const* d_in, const int* in_sizes, int n_in,
                              void* d_out, int out_size)
{
    const float* query = (const float*)d_in[0];
    const float* key   = (const float*)d_in[1];
    const float* value = (const float*)d_in[2];
    const int*   mask  = (const int*)d_in[3];
    const float* Wq = (const float*)d_in[4];
    const float* bq = (const float*)d_in[5];
    const float* Wk = (const float*)d_in[6];
    const float* bk = (const float*)d_in[7];
    const float* Wv = (const float*)d_in[8];
    const float* bv = (const float*)d_in[9];
    const float* Wo = (const float*)d_in[10];
    const float* bo = (const float*)d_in[11];
    const float* gamma = (const float*)d_in[12];
    const float* beta  = (const float*)d_in[13];
    float* out = (float*)d_out;

    float *Qb, *Kb, *Vb, *Cb, *AttnScratch;
    cudaGetSymbolAddress((void**)&Qb, g_Q);
    cudaGetSymbolAddress((void**)&Kb, g_Kb);
    cudaGetSymbolAddress((void**)&Vb, g_Vb);
    cudaGetSymbolAddress((void**)&Cb, g_CTX);
    cudaGetSymbolAddress((void**)&AttnScratch, g_ATTN);

    // attn goes straight into d_out if the output buffer carries it (tuple concat)
    float* attn = ((long long)out_size >= (long long)OUT0 + ATTN_ELEMS)
                      ? (out + OUT0) : AttnScratch;

    dim3 gQKV(Dc / 128, MR / 128, 3);   // (8, 64, 3)
    qkv_proj<<<gQKV, 256>>>(query, key, value, Wq, Wk, Wv, bq, bk, bv,
                            Qb, Kb, Vb);

    dim3 gS(Sc / 128, Sc / 128, Bc * Hc);  // (16,16,64)
    gemm_scores<<<gS, 256>>>(Qb, Kb, mask, attn);

    softmax_rows<<<Bc * Hc * Sc, 256>>>(attn);  // 131072 rows

    dim3 gC(1, Sc / 128, Bc * Hc);      // (1,16,64)
    gemm_ctx<<<gC, 256>>>(attn, Vb, Cb);

    // out-proj + bias + residual -> x (reuse Qb as x buffer)
    dim3 gProj(Dc / 128, MR / 128);     // (8, 64)
    gemm_out_proj<<<gProj, 256>>>(Cb, Wo, bo, query, Qb);

    layernorm_rows<<<MR, 256>>>(Qb, gamma, beta, out);
}